// round 13
// baseline (speedup 1.0000x reference)
#include <cuda_runtime.h>
#include <cuda_fp16.h>
#include <math.h>
#include <stdint.h>

// Problem constants
#define Bb   16
#define Ss   4096
#define Hh   12
#define Dd   64
constexpr int M = Bb * Ss;   // 65536
constexpr int NQKV = 2304;   // merged Q|K|V columns

// ---------------------------------------------------------------------------
// Scratch (device globals)
// ---------------------------------------------------------------------------
__device__ __half g_qkv16[(size_t)M * NQKV];      // Q | K | V fp16
__device__ __half g_xh[(size_t)M * 768];          // x fp16
__device__ __half g_a16[(size_t)M * 768];         // attention output fp16
__device__ __half g_wh[(size_t)NQKV * 768];       // Wqkv^T fp16
__device__ __half g_woh[768 * 768];               // Wo^T fp16
__device__ float  g_biasc[NQKV];
__device__ float  g_kvp[4][Bb * Hh][64 * 72];     // kv partials (fp32)
__device__ __half g_kvt[Bb * Hh][64 * 72];        // reduced kv+ksum (fp16)

// ---------------------------------------------------------------------------
// PTX helpers (sm_80-compatible: cp.async, ldmatrix, mma.sync)
// ---------------------------------------------------------------------------
__device__ __forceinline__ uint32_t smem_u32(const void* p) {
    uint32_t a;
    asm("{ .reg .u64 t; cvta.to.shared.u64 t, %1; cvt.u32.u64 %0, t; }"
        : "=r"(a) : "l"(p));
    return a;
}

__device__ __forceinline__ void cpa16(uint32_t dst, const void* src) {
    asm volatile("cp.async.cg.shared.global [%0], [%1], 16;" :: "r"(dst), "l"(src) : "memory");
}
#define CP_COMMIT() asm volatile("cp.async.commit_group;" ::: "memory")
#define CP_WAIT(n)  asm volatile("cp.async.wait_group %0;" :: "n"(n) : "memory")

__device__ __forceinline__ void ldsm4(uint32_t* r, uint32_t addr) {
    asm volatile("ldmatrix.sync.aligned.m8n8.x4.shared.b16 {%0,%1,%2,%3}, [%4];"
                 : "=r"(r[0]), "=r"(r[1]), "=r"(r[2]), "=r"(r[3]) : "r"(addr));
}
__device__ __forceinline__ void ldsm4t(uint32_t* r, uint32_t addr) {
    asm volatile("ldmatrix.sync.aligned.m8n8.x4.trans.shared.b16 {%0,%1,%2,%3}, [%4];"
                 : "=r"(r[0]), "=r"(r[1]), "=r"(r[2]), "=r"(r[3]) : "r"(addr));
}
__device__ __forceinline__ void ldsm2t(uint32_t* r, uint32_t addr) {
    asm volatile("ldmatrix.sync.aligned.m8n8.x2.trans.shared.b16 {%0,%1}, [%2];"
                 : "=r"(r[0]), "=r"(r[1]) : "r"(addr));
}

__device__ __forceinline__ void mma_f16(float* c, const uint32_t* a, const uint32_t* b) {
    asm volatile(
        "mma.sync.aligned.m16n8k16.row.col.f32.f16.f16.f32 "
        "{%0,%1,%2,%3}, {%4,%5,%6,%7}, {%8,%9}, {%0,%1,%2,%3};"
        : "+f"(c[0]), "+f"(c[1]), "+f"(c[2]), "+f"(c[3])
        : "r"(a[0]), "r"(a[1]), "r"(a[2]), "r"(a[3]), "r"(b[0]), "r"(b[1]));
}

__device__ __forceinline__ float epi_f(float v, float mk, int epi) {
    if (epi >= 1) v *= mk;
    if (epi == 2) { v = (v > 0.0f) ? (v + 1.0f) : expf(v); v *= 0.125f; }
    return v;
}

// ---------------------------------------------------------------------------
// fp16 single-term GEMM:  C = A(fp16) @ B^T   (B pre-transposed [N][K])
// CTA tile 128x256x32, 256 threads (8 warps, 2x4, warp tile 64x64),
// 5-stage cp.async ring (123KB smem, 1 CTA/SM) to hide latency at low occ.
// Traffic per output: 4/128 (vs 6/128 for the 128x128 config).
// mode 1 (QKV): fp16 out (ld 2304); epi: elu for bx<6, mask else
// mode 0 (out): fp32 out (ld 768); plain bias
// ---------------------------------------------------------------------------
constexpr int F_STAGE = 24576;       // A 8KB | B 16KB
constexpr int F_SMEM  = 5 * F_STAGE; // 122880
constexpr int FA = 0, FB = 8192;

__device__ __forceinline__ void stage_load_f16(
    uint32_t sbase,
    const __half* __restrict__ A, const __half* __restrict__ B,
    int mb, int nb, int k0, int tid)
{
    // A: 128 rows x 4 chunks = 512 slots
    #pragma unroll
    for (int t = 0; t < 2; t++) {
        const int lin = tid + t * 256;
        const int r = lin >> 2;
        const int c = lin & 3;
        const uint32_t so = (uint32_t)r * 64 + ((uint32_t)(c ^ ((r >> 1) & 3)) << 4);
        cpa16(sbase + FA + so, A + (size_t)(mb + r) * 768 + k0 + c * 8);
    }
    // B: 256 rows x 4 chunks = 1024 slots
    #pragma unroll
    for (int t = 0; t < 4; t++) {
        const int lin = tid + t * 256;
        const int r = lin >> 2;
        const int c = lin & 3;
        const uint32_t so = (uint32_t)r * 64 + ((uint32_t)(c ^ ((r >> 1) & 3)) << 4);
        cpa16(sbase + FB + so, B + (size_t)(nb + r) * 768 + k0 + c * 8);
    }
}

__global__ void __launch_bounds__(256, 1)
gemm_f16(const __half* __restrict__ A, const __half* __restrict__ B,
         const float* __restrict__ bias, const float* __restrict__ mask,
         float* __restrict__ C32, __half* __restrict__ C16, int mode)
{
    extern __shared__ char smraw[];
    const uint32_t sm0 = smem_u32(smraw);

    const int tid  = threadIdx.x;
    const int lane = tid & 31;
    const int warp = tid >> 5;
    const int wm = warp & 1;        // 2 warps in M -> 64 rows
    const int wn = warp >> 1;       // 4 warps in N -> 64 cols
    const int nb = blockIdx.x * 256;
    const int mb = blockIdx.y * 128;
    const int epi = (mode == 0) ? 0 : ((blockIdx.x < 6) ? 2 : 1);

    uint32_t baseA[4], maskA[4];
    const int arow0 = wm * 64 + (lane & 15);
    const uint32_t acs = (uint32_t)(lane >> 4);
    #pragma unroll
    for (int mt = 0; mt < 4; mt++) {
        const int r = arow0 + mt * 16;
        baseA[mt] = (uint32_t)r * 64;
        maskA[mt] = (uint32_t)((r >> 1) & 3);
    }
    uint32_t baseB[4], maskB[4];
    const int brow0 = wn * 64 + (lane & 7) + ((lane >> 4) << 3);
    const uint32_t bcs = (uint32_t)((lane >> 3) & 1);
    #pragma unroll
    for (int bt = 0; bt < 4; bt++) {
        const int r = brow0 + bt * 16;
        baseB[bt] = (uint32_t)r * 64;
        maskB[bt] = (uint32_t)((r >> 1) & 3);
    }

    float acc[4][8][4] = {};

    stage_load_f16(sm0 + 0 * F_STAGE, A, B, mb, nb, 0, tid);
    CP_COMMIT();
    stage_load_f16(sm0 + 1 * F_STAGE, A, B, mb, nb, 32, tid);
    CP_COMMIT();
    stage_load_f16(sm0 + 2 * F_STAGE, A, B, mb, nb, 64, tid);
    CP_COMMIT();
    stage_load_f16(sm0 + 3 * F_STAGE, A, B, mb, nb, 96, tid);
    CP_COMMIT();

    #pragma unroll 1
    for (int s = 0; s < 24; s++) {
        const int rem = 23 - s;   // stages still to be consumed after this one
        if (rem >= 3)      { CP_WAIT(3); }
        else if (rem == 2) { CP_WAIT(2); }
        else if (rem == 1) { CP_WAIT(1); }
        else               { CP_WAIT(0); }
        __syncthreads();

        const uint32_t sb = sm0 + (s % 5) * F_STAGE;
        #pragma unroll
        for (int ks = 0; ks < 2; ks++) {
            const uint32_t kc = (uint32_t)(ks * 2);

            uint32_t bf[8][2];
            #pragma unroll
            for (int bt = 0; bt < 4; bt++) {
                const uint32_t off = baseB[bt] + (((kc + bcs) ^ maskB[bt]) << 4);
                uint32_t tmp[4];
                ldsm4(tmp, sb + FB + off);
                bf[2 * bt][0] = tmp[0]; bf[2 * bt][1] = tmp[1];
                bf[2 * bt + 1][0] = tmp[2]; bf[2 * bt + 1][1] = tmp[3];
            }
            uint32_t a[4][4];
            #pragma unroll
            for (int mt = 0; mt < 4; mt++)
                ldsm4(a[mt], sb + FA + baseA[mt] + (((kc + acs) ^ maskA[mt]) << 4));

            #pragma unroll
            for (int mt = 0; mt < 4; mt++)
                #pragma unroll
                for (int nt = 0; nt < 8; nt++)
                    mma_f16(acc[mt][nt], a[mt], bf[nt]);
        }

        if (s + 4 < 24) {
            stage_load_f16(sm0 + ((s + 4) % 5) * F_STAGE, A, B,
                           mb, nb, (s + 4) * 32, tid);
            CP_COMMIT();
        }
    }

    // epilogue
    const int r0 = lane >> 2;
    const int c0 = (lane & 3) * 2;
    #pragma unroll
    for (int mt = 0; mt < 4; mt++) {
        const int mrow = mb + wm * 64 + mt * 16 + r0;
        const float mk0 = (epi >= 1) ? mask[mrow] : 1.0f;
        const float mk1 = (epi >= 1) ? mask[mrow + 8] : 1.0f;
        #pragma unroll
        for (int nt = 0; nt < 8; nt++) {
            const int col = nb + wn * 64 + nt * 8 + c0;
            const float b0 = bias[col], b1 = bias[col + 1];
            const float v00 = epi_f(acc[mt][nt][0] + b0, mk0, epi);
            const float v01 = epi_f(acc[mt][nt][1] + b1, mk0, epi);
            const float v10 = epi_f(acc[mt][nt][2] + b0, mk1, epi);
            const float v11 = epi_f(acc[mt][nt][3] + b1, mk1, epi);
            if (mode == 1) {
                *reinterpret_cast<__half2*>(C16 + (size_t)mrow * NQKV + col) =
                    __floats2half2_rn(v00, v01);
                *reinterpret_cast<__half2*>(C16 + (size_t)(mrow + 8) * NQKV + col) =
                    __floats2half2_rn(v10, v11);
            } else {
                *reinterpret_cast<float2*>(C32 + (size_t)mrow * 768 + col) =
                    make_float2(v00, v01);
                *reinterpret_cast<float2*>(C32 + (size_t)(mrow + 8) * 768 + col) =
                    make_float2(v10, v11);
            }
        }
    }
}

// ---------------------------------------------------------------------------
// Prep kernels
// ---------------------------------------------------------------------------
__global__ void __launch_bounds__(256)
cvt_x_kernel(const float* __restrict__ x, __half* __restrict__ xh)
{
    const size_t i = ((size_t)blockIdx.x * 256 + threadIdx.x) * 8;
    const float4 v0 = *reinterpret_cast<const float4*>(x + i);
    const float4 v1 = *reinterpret_cast<const float4*>(x + i + 4);
    __half2 h[4];
    h[0] = __floats2half2_rn(v0.x, v0.y);
    h[1] = __floats2half2_rn(v0.z, v0.w);
    h[2] = __floats2half2_rn(v1.x, v1.y);
    h[3] = __floats2half2_rn(v1.z, v1.w);
    *reinterpret_cast<uint4*>(xh + i) = *reinterpret_cast<uint4*>(h);
}

// transpose + fp16 convert for ALL weights in one launch.
__global__ void __launch_bounds__(256)
wt16_all_kernel(const float* __restrict__ Wq, const float* __restrict__ Wk,
                const float* __restrict__ Wv, const float* __restrict__ Wo,
                __half* __restrict__ wh, __half* __restrict__ woh)
{
    __shared__ float t[32][33];
    const int z = blockIdx.z;
    const float* W = (z == 0) ? Wq : (z == 1) ? Wk : (z == 2) ? Wv : Wo;
    __half* dst = (z == 3) ? woh : wh + (size_t)z * 768 * 768;

    const int bx = blockIdx.x * 32, by = blockIdx.y * 32;
    const int tx = threadIdx.x, ty = threadIdx.y;
    #pragma unroll
    for (int i = 0; i < 32; i += 8)
        t[ty + i][tx] = W[(size_t)(by + ty + i) * 768 + bx + tx];
    __syncthreads();
    #pragma unroll
    for (int i = 0; i < 32; i += 8)
        dst[(size_t)(bx + ty + i) * 768 + by + tx] = __float2half(t[tx][ty + i]);
}

__global__ void bias_concat_kernel(const float* bq, const float* bk, const float* bv,
                                   float* out)
{
    const int i = threadIdx.x;
    const float* src = (blockIdx.x == 0) ? bq : (blockIdx.x == 1) ? bk : bv;
    out[blockIdx.x * 768 + i] = src[i];
}

// ---------------------------------------------------------------------------
// kv = K^T V (+ ksum in col 64) via fp16 tensor cores.
// grid (192, 4): one (b,h) x 1024-seq chunk per block, 128 threads.
// ---------------------------------------------------------------------------
__global__ void __launch_bounds__(128)
kv_tc_kernel(const __half* __restrict__ QKV16)
{
    __shared__ __half kb[2][64][72];
    __shared__ __half vb[2][64][72];

    const int bh = blockIdx.x, ch = blockIdx.y;
    const int b = bh / Hh, h = bh % Hh;
    const int tid = threadIdx.x, lane = tid & 31, warp = tid >> 5;

    {
        const int bf = tid >> 6, r = tid & 63;
        vb[bf][r][64] = __float2half(1.0f);
        #pragma unroll
        for (int c = 65; c < 72; c++) vb[bf][r][c] = __float2half(0.0f);
    }
    __syncthreads();

    const int chunk0 = ch * 1024;
    const int d0 = warp * 16;

    #define KV_LOAD(st, s0)                                                       \
        do {                                                                      \
            _Pragma("unroll")                                                     \
            for (int t = 0; t < 4; t++) {                                         \
                const int lin = tid + t * 128;                                    \
                const int r = lin >> 3, c = lin & 7;                              \
                const size_t base =                                               \
                    ((size_t)(b * Ss + (s0) + r)) * NQKV + h * 64 + c * 8;        \
                cpa16(smem_u32(&kb[st][r][c * 8]), QKV16 + base + 768);           \
                cpa16(smem_u32(&vb[st][r][c * 8]), QKV16 + base + 1536);          \
            }                                                                     \
            CP_COMMIT();                                                          \
        } while (0)

    float acc[9][4] = {};

    KV_LOAD(0, chunk0);
    KV_LOAD(1, chunk0 + 64);

    const int g = lane >> 3, l = lane & 7;

    #pragma unroll 1
    for (int it = 0; it < 16; it++) {
        if (it < 15) { CP_WAIT(1); } else { CP_WAIT(0); }
        __syncthreads();

        const int st = it & 1;
        #pragma unroll
        for (int ks = 0; ks < 4; ks++) {
            const int srow = ks * 16 + ((g & 2) ? 8 : 0) + l;
            const int scol = d0 + ((g & 1) ? 8 : 0);
            uint32_t a[4];
            ldsm4t(a, smem_u32(&kb[st][srow][scol]));

            uint32_t bfrag[9][2];
            const int vrow = ks * 16 + ((g & 1) ? 8 : 0) + l;
            #pragma unroll
            for (int np = 0; np < 4; np++) {
                const int vcol = np * 16 + ((g & 2) ? 8 : 0);
                uint32_t t4[4];
                ldsm4t(t4, smem_u32(&vb[st][vrow][vcol]));
                bfrag[2 * np][0] = t4[0];     bfrag[2 * np][1] = t4[1];
                bfrag[2 * np + 1][0] = t4[2]; bfrag[2 * np + 1][1] = t4[3];
            }
            {
                const int vr2 = ks * 16 + ((lane >> 3) & 1) * 8 + l;
                uint32_t t2[2];
                ldsm2t(t2, smem_u32(&vb[st][vr2][64]));
                bfrag[8][0] = t2[0]; bfrag[8][1] = t2[1];
            }
            #pragma unroll
            for (int nt = 0; nt < 9; nt++) mma_f16(acc[nt], a, bfrag[nt]);
        }
        __syncthreads();
        if (it + 2 < 16) KV_LOAD(st, chunk0 + (it + 2) * 64);
    }
    #undef KV_LOAD

    float* dst = &g_kvp[ch][bh][0];
    const int r = lane >> 2, cp = (lane & 3) * 2;
    #pragma unroll
    for (int nt = 0; nt < 9; nt++) {
        const int col = nt * 8 + cp;
        *reinterpret_cast<float2*>(dst + (d0 + r) * 72 + col) =
            make_float2(acc[nt][0], acc[nt][1]);
        *reinterpret_cast<float2*>(dst + (d0 + r + 8) * 72 + col) =
            make_float2(acc[nt][2], acc[nt][3]);
    }
}

__global__ void __launch_bounds__(128)
kv_reduce_kernel()
{
    const int bh = blockIdx.x;
    for (int i = threadIdx.x; i < 64 * 72; i += 128) {
        const float s = g_kvp[0][bh][i] + g_kvp[1][bh][i]
                      + g_kvp[2][bh][i] + g_kvp[3][bh][i];
        g_kvt[bh][i] = __float2half(s);
    }
}

// ---------------------------------------------------------------------------
// num|den = Q @ kv[64x72] (col 64 = den); out = num/den -> fp16 a16.
// ---------------------------------------------------------------------------
__global__ void __launch_bounds__(128)
num_tc_kernel(const __half* __restrict__ QKV16, __half* __restrict__ A16)
{
    __shared__ __half kvs[64][72];

    const int bh = blockIdx.x;
    const int b = bh / Hh, h = bh % Hh;
    const int tid = threadIdx.x, lane = tid & 31, warp = tid >> 5;
    const int s0 = blockIdx.y * 256;

    {
        const uint32_t* src = reinterpret_cast<const uint32_t*>(&g_kvt[bh][0]);
        uint32_t* dst = reinterpret_cast<uint32_t*>(&kvs[0][0]);
        for (int i = tid; i < 64 * 72 / 2; i += 128) dst[i] = src[i];
    }
    __syncthreads();

    uint32_t bfr[4][9][2];
    const int g = lane >> 3, l = lane & 7;
    #pragma unroll
    for (int ks = 0; ks < 4; ks++) {
        const int vrow = ks * 16 + ((g & 1) ? 8 : 0) + l;
        #pragma unroll
        for (int np = 0; np < 4; np++) {
            const int vcol = np * 16 + ((g & 2) ? 8 : 0);
            uint32_t t4[4];
            ldsm4t(t4, smem_u32(&kvs[vrow][vcol]));
            bfr[ks][2 * np][0] = t4[0];     bfr[ks][2 * np][1] = t4[1];
            bfr[ks][2 * np + 1][0] = t4[2]; bfr[ks][2 * np + 1][1] = t4[3];
        }
        const int vr2 = ks * 16 + ((lane >> 3) & 1) * 8 + l;
        uint32_t t2[2];
        ldsm2t(t2, smem_u32(&kvs[vr2][64]));
        bfr[ks][8][0] = t2[0]; bfr[ks][8][1] = t2[1];
    }

    const uint32_t* Q32 = reinterpret_cast<const uint32_t*>(QKV16);
    const int rbase = b * Ss + s0 + warp * 64;

    #pragma unroll 1
    for (int mt = 0; mt < 4; mt++) {
        float acc[9][4] = {};
        const int row = rbase + mt * 16 + (lane >> 2);
        #pragma unroll
        for (int ks = 0; ks < 4; ks++) {
            const int cb = h * 64 + ks * 16 + (lane & 3) * 2;
            uint32_t a[4];
            a[0] = Q32[((size_t)row * NQKV + cb) >> 1];
            a[1] = Q32[((size_t)(row + 8) * NQKV + cb) >> 1];
            a[2] = Q32[((size_t)row * NQKV + cb + 8) >> 1];
            a[3] = Q32[((size_t)(row + 8) * NQKV + cb + 8) >> 1];
            #pragma unroll
            for (int nt = 0; nt < 9; nt++) mma_f16(acc[nt], a, bfr[ks][nt]);
        }

        const float den0 = __shfl_sync(0xFFFFFFFFu, acc[8][0], lane & 28);
        const float den1 = __shfl_sync(0xFFFFFFFFu, acc[8][2], lane & 28);
        const float i0 = 1.0f / den0, i1 = 1.0f / den1;
        #pragma unroll
        for (int nt = 0; nt < 8; nt++) {
            const int col = h * 64 + nt * 8 + (lane & 3) * 2;
            *reinterpret_cast<__half2*>(A16 + (size_t)row * 768 + col) =
                __floats2half2_rn(acc[nt][0] * i0, acc[nt][1] * i0);
            *reinterpret_cast<__half2*>(A16 + (size_t)(row + 8) * 768 + col) =
                __floats2half2_rn(acc[nt][2] * i1, acc[nt][3] * i1);
        }
    }
}

// ---------------------------------------------------------------------------
extern "C" void kernel_launch(void* const* d_in, const int* in_sizes, int n_in,
                              void* d_out, int out_size)
{
    const float* x    = (const float*)d_in[0];
    const float* mask = (const float*)d_in[1];
    const float* Wq   = (const float*)d_in[2];
    const float* bq   = (const float*)d_in[3];
    const float* Wk   = (const float*)d_in[4];
    const float* bk   = (const float*)d_in[5];
    const float* Wv   = (const float*)d_in[6];
    const float* bv   = (const float*)d_in[7];
    const float* Wo   = (const float*)d_in[8];
    const float* bo   = (const float*)d_in[9];
    float* out = (float*)d_out;

    float *biasc;
    __half *qkv16, *xh, *a16, *wh, *woh;
    cudaGetSymbolAddress((void**)&qkv16, g_qkv16);
    cudaGetSymbolAddress((void**)&xh,    g_xh);
    cudaGetSymbolAddress((void**)&a16,   g_a16);
    cudaGetSymbolAddress((void**)&wh,    g_wh);
    cudaGetSymbolAddress((void**)&woh,   g_woh);
    cudaGetSymbolAddress((void**)&biasc, g_biasc);

    cudaFuncSetAttribute(gemm_f16, cudaFuncAttributeMaxDynamicSharedMemorySize, F_SMEM);

    // prep
    cvt_x_kernel<<<(int)(((size_t)M * 768) / 8 / 256), 256>>>(x, xh);
    wt16_all_kernel<<<dim3(24, 24, 4), dim3(32, 8)>>>(Wq, Wk, Wv, Wo, wh, woh);
    bias_concat_kernel<<<3, 768>>>(bq, bk, bv, biasc);

    // merged QKV projection -> fp16 (single-term)
    gemm_f16<<<dim3(9, 512), 256, F_SMEM>>>(xh, wh, biasc, mask,
                                            nullptr, qkv16, 1);

    // linear-attention core (tensor cores)
    kv_tc_kernel<<<dim3(Bb * Hh, 4), 128>>>(qkv16);
    kv_reduce_kernel<<<Bb * Hh, 128>>>();
    num_tc_kernel<<<dim3(Bb * Hh, Ss / 256), 128>>>(qkv16, a16);

    // output projection -> fp32 d_out (single-term)
    gemm_f16<<<dim3(3, 512), 256, F_SMEM>>>(a16, woh, bo, mask,
                                            out, nullptr, 0);
}

// round 14
// speedup vs baseline: 1.3065x; 1.3065x over previous
#include <cuda_runtime.h>
#include <cuda_fp16.h>
#include <math.h>
#include <stdint.h>

// Problem constants
#define Bb   16
#define Ss   4096
#define Hh   12
#define Dd   64
constexpr int M = Bb * Ss;   // 65536
constexpr int NQKV = 2304;   // merged Q|K|V columns

// ---------------------------------------------------------------------------
// Scratch (device globals)
// ---------------------------------------------------------------------------
__device__ __half g_qkv16[(size_t)M * NQKV];      // Q | K | V fp16
__device__ __half g_xh[(size_t)M * 768];          // x fp16
__device__ __half g_a16[(size_t)M * 768];         // attention output fp16
__device__ __half g_wh[(size_t)NQKV * 768];       // Wqkv^T fp16
__device__ __half g_woh[768 * 768];               // Wo^T fp16
__device__ float  g_biasc[NQKV];
__device__ float  g_kvp[4][Bb * Hh][64 * 72];     // kv partials (fp32)

// ---------------------------------------------------------------------------
// PTX helpers (sm_80-compatible: cp.async, ldmatrix, mma.sync)
// ---------------------------------------------------------------------------
__device__ __forceinline__ uint32_t smem_u32(const void* p) {
    uint32_t a;
    asm("{ .reg .u64 t; cvta.to.shared.u64 t, %1; cvt.u32.u64 %0, t; }"
        : "=r"(a) : "l"(p));
    return a;
}

__device__ __forceinline__ void cpa16(uint32_t dst, const void* src) {
    asm volatile("cp.async.cg.shared.global [%0], [%1], 16;" :: "r"(dst), "l"(src) : "memory");
}
#define CP_COMMIT() asm volatile("cp.async.commit_group;" ::: "memory")
#define CP_WAIT(n)  asm volatile("cp.async.wait_group %0;" :: "n"(n) : "memory")

__device__ __forceinline__ void ldsm4(uint32_t* r, uint32_t addr) {
    asm volatile("ldmatrix.sync.aligned.m8n8.x4.shared.b16 {%0,%1,%2,%3}, [%4];"
                 : "=r"(r[0]), "=r"(r[1]), "=r"(r[2]), "=r"(r[3]) : "r"(addr));
}
__device__ __forceinline__ void ldsm4t(uint32_t* r, uint32_t addr) {
    asm volatile("ldmatrix.sync.aligned.m8n8.x4.trans.shared.b16 {%0,%1,%2,%3}, [%4];"
                 : "=r"(r[0]), "=r"(r[1]), "=r"(r[2]), "=r"(r[3]) : "r"(addr));
}
__device__ __forceinline__ void ldsm2t(uint32_t* r, uint32_t addr) {
    asm volatile("ldmatrix.sync.aligned.m8n8.x2.trans.shared.b16 {%0,%1}, [%2];"
                 : "=r"(r[0]), "=r"(r[1]) : "r"(addr));
}

__device__ __forceinline__ void mma_f16(float* c, const uint32_t* a, const uint32_t* b) {
    asm volatile(
        "mma.sync.aligned.m16n8k16.row.col.f32.f16.f16.f32 "
        "{%0,%1,%2,%3}, {%4,%5,%6,%7}, {%8,%9}, {%0,%1,%2,%3};"
        : "+f"(c[0]), "+f"(c[1]), "+f"(c[2]), "+f"(c[3])
        : "r"(a[0]), "r"(a[1]), "r"(a[2]), "r"(a[3]), "r"(b[0]), "r"(b[1]));
}

__device__ __forceinline__ float epi_f(float v, float mk, int epi) {
    if (epi >= 1) v *= mk;
    if (epi == 2) { v = (v > 0.0f) ? (v + 1.0f) : __expf(v); v *= 0.125f; }
    return v;
}

// ---------------------------------------------------------------------------
// fp16 single-term GEMM:  C = A(fp16) @ B^T   (B pre-transposed [N][K])
// CTA tile 128x128x64 (two 32-wide sub-tiles/stage), 256 threads
// (8 warps, warp tile 64x32), 3-stage cp.async ring, 2 CTAs/SM.
// Smem/stage: A 16K | B 16K = 32KB. XOR swizzle on 16B chunks per sub-tile.
// mode 1 (QKV): fp16 out (ld 2304); epi: elu for bx<12, mask else
// mode 0 (out): fp32 out (ld 768); plain bias
// ---------------------------------------------------------------------------
constexpr int F_STAGE = 32768;
constexpr int F_SMEM  = 3 * F_STAGE;
constexpr int FA = 0, FB = 16384;   // each: 2 x 8KB sub-tiles

__device__ __forceinline__ void stage_load_f16(
    uint32_t sbase,
    const __half* __restrict__ A, const __half* __restrict__ B,
    int mb, int nb, int k0, int tid)
{
    #pragma unroll
    for (int sub = 0; sub < 2; sub++) {
        const int ks0 = k0 + sub * 32;
        const uint32_t sboff = (uint32_t)sub * 8192;
        #pragma unroll
        for (int t = 0; t < 2; t++) {
            const int lin = tid + t * 256;   // 512 slots: 128 rows x 4 chunks
            const int r = lin >> 2;
            const int c = lin & 3;
            const uint32_t so = (uint32_t)r * 64 + ((uint32_t)(c ^ ((r >> 1) & 3)) << 4);
            cpa16(sbase + FA + sboff + so, A + (size_t)(mb + r) * 768 + ks0 + c * 8);
            cpa16(sbase + FB + sboff + so, B + (size_t)(nb + r) * 768 + ks0 + c * 8);
        }
    }
}

__global__ void __launch_bounds__(256, 2)
gemm_f16(const __half* __restrict__ A, const __half* __restrict__ B,
         const float* __restrict__ bias, const float* __restrict__ mask,
         float* __restrict__ C32, __half* __restrict__ C16, int mode)
{
    extern __shared__ char smraw[];
    const uint32_t sm0 = smem_u32(smraw);

    const int tid  = threadIdx.x;
    const int lane = tid & 31;
    const int warp = tid >> 5;
    const int wm = warp & 1;        // 2 warps in M -> 64 rows
    const int wn = warp >> 1;       // 4 warps in N -> 32 cols
    const int nb = blockIdx.x * 128;
    const int mb = blockIdx.y * 128;
    const int epi = (mode == 0) ? 0 : ((blockIdx.x < 12) ? 2 : 1);

    uint32_t baseA[4], maskA[4];
    const int arow0 = wm * 64 + (lane & 15);
    const uint32_t acs = (uint32_t)(lane >> 4);
    #pragma unroll
    for (int mt = 0; mt < 4; mt++) {
        const int r = arow0 + mt * 16;
        baseA[mt] = (uint32_t)r * 64;
        maskA[mt] = (uint32_t)((r >> 1) & 3);
    }
    uint32_t baseB[2], maskB[2];
    const int brow0 = wn * 32 + (lane & 7) + ((lane >> 4) << 3);
    const uint32_t bcs = (uint32_t)((lane >> 3) & 1);
    #pragma unroll
    for (int bt = 0; bt < 2; bt++) {
        const int r = brow0 + bt * 16;
        baseB[bt] = (uint32_t)r * 64;
        maskB[bt] = (uint32_t)((r >> 1) & 3);
    }

    float acc[4][4][4] = {};

    stage_load_f16(sm0 + 0 * F_STAGE, A, B, mb, nb, 0, tid);
    CP_COMMIT();
    stage_load_f16(sm0 + 1 * F_STAGE, A, B, mb, nb, 64, tid);
    CP_COMMIT();

    #pragma unroll 1
    for (int s = 0; s < 12; s++) {
        if (s < 11) { CP_WAIT(1); } else { CP_WAIT(0); }
        __syncthreads();

        const uint32_t sb = sm0 + (s % 3) * F_STAGE;
        #pragma unroll
        for (int sub = 0; sub < 2; sub++) {
            const uint32_t sbA = sb + FA + sub * 8192;
            const uint32_t sbB = sb + FB + sub * 8192;
            #pragma unroll
            for (int ks = 0; ks < 2; ks++) {
                const uint32_t kc = (uint32_t)(ks * 2);

                uint32_t bf[4][2];
                #pragma unroll
                for (int bt = 0; bt < 2; bt++) {
                    const uint32_t off = baseB[bt] + (((kc + bcs) ^ maskB[bt]) << 4);
                    uint32_t tmp[4];
                    ldsm4(tmp, sbB + off);
                    bf[2 * bt][0] = tmp[0]; bf[2 * bt][1] = tmp[1];
                    bf[2 * bt + 1][0] = tmp[2]; bf[2 * bt + 1][1] = tmp[3];
                }
                uint32_t a[4][4];
                #pragma unroll
                for (int mt = 0; mt < 4; mt++)
                    ldsm4(a[mt], sbA + baseA[mt] + (((kc + acs) ^ maskA[mt]) << 4));

                #pragma unroll
                for (int mt = 0; mt < 4; mt++)
                    #pragma unroll
                    for (int nt = 0; nt < 4; nt++)
                        mma_f16(acc[mt][nt], a[mt], bf[nt]);
            }
        }

        if (s + 2 < 12) {
            stage_load_f16(sm0 + ((s + 2) % 3) * F_STAGE, A, B,
                           mb, nb, (s + 2) * 64, tid);
            CP_COMMIT();
        }
    }

    // epilogue
    const int r0 = lane >> 2;
    const int c0 = (lane & 3) * 2;
    #pragma unroll
    for (int mt = 0; mt < 4; mt++) {
        const int mrow = mb + wm * 64 + mt * 16 + r0;
        const float mk0 = (epi >= 1) ? mask[mrow] : 1.0f;
        const float mk1 = (epi >= 1) ? mask[mrow + 8] : 1.0f;
        #pragma unroll
        for (int nt = 0; nt < 4; nt++) {
            const int col = nb + wn * 32 + nt * 8 + c0;
            const float b0 = bias[col], b1 = bias[col + 1];
            const float v00 = epi_f(acc[mt][nt][0] + b0, mk0, epi);
            const float v01 = epi_f(acc[mt][nt][1] + b1, mk0, epi);
            const float v10 = epi_f(acc[mt][nt][2] + b0, mk1, epi);
            const float v11 = epi_f(acc[mt][nt][3] + b1, mk1, epi);
            if (mode == 1) {
                *reinterpret_cast<__half2*>(C16 + (size_t)mrow * NQKV + col) =
                    __floats2half2_rn(v00, v01);
                *reinterpret_cast<__half2*>(C16 + (size_t)(mrow + 8) * NQKV + col) =
                    __floats2half2_rn(v10, v11);
            } else {
                *reinterpret_cast<float2*>(C32 + (size_t)mrow * 768 + col) =
                    make_float2(v00, v01);
                *reinterpret_cast<float2*>(C32 + (size_t)(mrow + 8) * 768 + col) =
                    make_float2(v10, v11);
            }
        }
    }
}

// ---------------------------------------------------------------------------
// Prep kernels
// ---------------------------------------------------------------------------
__global__ void __launch_bounds__(256)
cvt_x_kernel(const float* __restrict__ x, __half* __restrict__ xh)
{
    const size_t i = ((size_t)blockIdx.x * 256 + threadIdx.x) * 8;
    const float4 v0 = *reinterpret_cast<const float4*>(x + i);
    const float4 v1 = *reinterpret_cast<const float4*>(x + i + 4);
    __half2 h[4];
    h[0] = __floats2half2_rn(v0.x, v0.y);
    h[1] = __floats2half2_rn(v0.z, v0.w);
    h[2] = __floats2half2_rn(v1.x, v1.y);
    h[3] = __floats2half2_rn(v1.z, v1.w);
    *reinterpret_cast<uint4*>(xh + i) = *reinterpret_cast<uint4*>(h);
}

// transpose + fp16 convert for ALL weights in one launch; z=0 block row 0 also
// writes the concatenated bias.
__global__ void __launch_bounds__(256)
wt16_all_kernel(const float* __restrict__ Wq, const float* __restrict__ Wk,
                const float* __restrict__ Wv, const float* __restrict__ Wo,
                const float* __restrict__ bq, const float* __restrict__ bk,
                const float* __restrict__ bv,
                __half* __restrict__ wh, __half* __restrict__ woh,
                float* __restrict__ biasc)
{
    __shared__ float t[32][33];
    const int z = blockIdx.z;
    const float* W = (z == 0) ? Wq : (z == 1) ? Wk : (z == 2) ? Wv : Wo;
    __half* dst = (z == 3) ? woh : wh + (size_t)z * 768 * 768;

    const int bx = blockIdx.x * 32, by = blockIdx.y * 32;
    const int tx = threadIdx.x, ty = threadIdx.y;

    // bias concat piggyback: z<3, by==0, one value per (bx, tx) pair row
    if (z < 3 && blockIdx.y == 0 && ty == 0) {
        const float* src = (z == 0) ? bq : (z == 1) ? bk : bv;
        biasc[z * 768 + bx + tx] = src[bx + tx];
    }

    #pragma unroll
    for (int i = 0; i < 32; i += 8)
        t[ty + i][tx] = W[(size_t)(by + ty + i) * 768 + bx + tx];
    __syncthreads();
    #pragma unroll
    for (int i = 0; i < 32; i += 8)
        dst[(size_t)(bx + ty + i) * 768 + by + tx] = __float2half(t[tx][ty + i]);
}

// ---------------------------------------------------------------------------
// kv = K^T V (+ ksum in col 64) via fp16 tensor cores.
// grid (192, 4): one (b,h) x 1024-seq chunk per block, 128 threads.
// ---------------------------------------------------------------------------
__global__ void __launch_bounds__(128)
kv_tc_kernel(const __half* __restrict__ QKV16)
{
    __shared__ __half kb[2][64][72];
    __shared__ __half vb[2][64][72];

    const int bh = blockIdx.x, ch = blockIdx.y;
    const int b = bh / Hh, h = bh % Hh;
    const int tid = threadIdx.x, lane = tid & 31, warp = tid >> 5;

    {
        const int bf = tid >> 6, r = tid & 63;
        vb[bf][r][64] = __float2half(1.0f);
        #pragma unroll
        for (int c = 65; c < 72; c++) vb[bf][r][c] = __float2half(0.0f);
    }
    __syncthreads();

    const int chunk0 = ch * 1024;
    const int d0 = warp * 16;

    #define KV_LOAD(st, s0)                                                       \
        do {                                                                      \
            _Pragma("unroll")                                                     \
            for (int t = 0; t < 4; t++) {                                         \
                const int lin = tid + t * 128;                                    \
                const int r = lin >> 3, c = lin & 7;                              \
                const size_t base =                                               \
                    ((size_t)(b * Ss + (s0) + r)) * NQKV + h * 64 + c * 8;        \
                cpa16(smem_u32(&kb[st][r][c * 8]), QKV16 + base + 768);           \
                cpa16(smem_u32(&vb[st][r][c * 8]), QKV16 + base + 1536);          \
            }                                                                     \
            CP_COMMIT();                                                          \
        } while (0)

    float acc[9][4] = {};

    KV_LOAD(0, chunk0);
    KV_LOAD(1, chunk0 + 64);

    const int g = lane >> 3, l = lane & 7;

    #pragma unroll 1
    for (int it = 0; it < 16; it++) {
        if (it < 15) { CP_WAIT(1); } else { CP_WAIT(0); }
        __syncthreads();

        const int st = it & 1;
        #pragma unroll
        for (int ks = 0; ks < 4; ks++) {
            const int srow = ks * 16 + ((g & 2) ? 8 : 0) + l;
            const int scol = d0 + ((g & 1) ? 8 : 0);
            uint32_t a[4];
            ldsm4t(a, smem_u32(&kb[st][srow][scol]));

            uint32_t bfrag[9][2];
            const int vrow = ks * 16 + ((g & 1) ? 8 : 0) + l;
            #pragma unroll
            for (int np = 0; np < 4; np++) {
                const int vcol = np * 16 + ((g & 2) ? 8 : 0);
                uint32_t t4[4];
                ldsm4t(t4, smem_u32(&vb[st][vrow][vcol]));
                bfrag[2 * np][0] = t4[0];     bfrag[2 * np][1] = t4[1];
                bfrag[2 * np + 1][0] = t4[2]; bfrag[2 * np + 1][1] = t4[3];
            }
            {
                const int vr2 = ks * 16 + ((lane >> 3) & 1) * 8 + l;
                uint32_t t2[2];
                ldsm2t(t2, smem_u32(&vb[st][vr2][64]));
                bfrag[8][0] = t2[0]; bfrag[8][1] = t2[1];
            }
            #pragma unroll
            for (int nt = 0; nt < 9; nt++) mma_f16(acc[nt], a, bfrag[nt]);
        }
        __syncthreads();
        if (it + 2 < 16) KV_LOAD(st, chunk0 + (it + 2) * 64);
    }
    #undef KV_LOAD

    float* dst = &g_kvp[ch][bh][0];
    const int r = lane >> 2, cp = (lane & 3) * 2;
    #pragma unroll
    for (int nt = 0; nt < 9; nt++) {
        const int col = nt * 8 + cp;
        *reinterpret_cast<float2*>(dst + (d0 + r) * 72 + col) =
            make_float2(acc[nt][0], acc[nt][1]);
        *reinterpret_cast<float2*>(dst + (d0 + r + 8) * 72 + col) =
            make_float2(acc[nt][2], acc[nt][3]);
    }
}

// ---------------------------------------------------------------------------
// num|den = Q @ kv[64x72] (col 64 = den); out = num/den -> fp16 a16.
// Reduction of the 4 kv partials is fused into the smem load phase.
// ---------------------------------------------------------------------------
__global__ void __launch_bounds__(128)
num_tc_kernel(const __half* __restrict__ QKV16, __half* __restrict__ A16)
{
    __shared__ __half kvs[64][72];

    const int bh = blockIdx.x;
    const int b = bh / Hh, h = bh % Hh;
    const int tid = threadIdx.x, lane = tid & 31, warp = tid >> 5;
    const int s0 = blockIdx.y * 256;

    {
        __half* dst = &kvs[0][0];
        for (int i = tid * 2; i < 64 * 72; i += 256) {
            const float a0 = g_kvp[0][bh][i] + g_kvp[1][bh][i]
                           + g_kvp[2][bh][i] + g_kvp[3][bh][i];
            const float a1 = g_kvp[0][bh][i + 1] + g_kvp[1][bh][i + 1]
                           + g_kvp[2][bh][i + 1] + g_kvp[3][bh][i + 1];
            *reinterpret_cast<__half2*>(dst + i) = __floats2half2_rn(a0, a1);
        }
    }
    __syncthreads();

    uint32_t bfr[4][9][2];
    const int g = lane >> 3, l = lane & 7;
    #pragma unroll
    for (int ks = 0; ks < 4; ks++) {
        const int vrow = ks * 16 + ((g & 1) ? 8 : 0) + l;
        #pragma unroll
        for (int np = 0; np < 4; np++) {
            const int vcol = np * 16 + ((g & 2) ? 8 : 0);
            uint32_t t4[4];
            ldsm4t(t4, smem_u32(&kvs[vrow][vcol]));
            bfr[ks][2 * np][0] = t4[0];     bfr[ks][2 * np][1] = t4[1];
            bfr[ks][2 * np + 1][0] = t4[2]; bfr[ks][2 * np + 1][1] = t4[3];
        }
        const int vr2 = ks * 16 + ((lane >> 3) & 1) * 8 + l;
        uint32_t t2[2];
        ldsm2t(t2, smem_u32(&kvs[vr2][64]));
        bfr[ks][8][0] = t2[0]; bfr[ks][8][1] = t2[1];
    }

    const uint32_t* Q32 = reinterpret_cast<const uint32_t*>(QKV16);
    const int rbase = b * Ss + s0 + warp * 64;

    #pragma unroll 1
    for (int mt = 0; mt < 4; mt++) {
        float acc[9][4] = {};
        const int row = rbase + mt * 16 + (lane >> 2);
        #pragma unroll
        for (int ks = 0; ks < 4; ks++) {
            const int cb = h * 64 + ks * 16 + (lane & 3) * 2;
            uint32_t a[4];
            a[0] = Q32[((size_t)row * NQKV + cb) >> 1];
            a[1] = Q32[((size_t)(row + 8) * NQKV + cb) >> 1];
            a[2] = Q32[((size_t)row * NQKV + cb + 8) >> 1];
            a[3] = Q32[((size_t)(row + 8) * NQKV + cb + 8) >> 1];
            #pragma unroll
            for (int nt = 0; nt < 9; nt++) mma_f16(acc[nt], a, bfr[ks][nt]);
        }

        const float den0 = __shfl_sync(0xFFFFFFFFu, acc[8][0], lane & 28);
        const float den1 = __shfl_sync(0xFFFFFFFFu, acc[8][2], lane & 28);
        const float i0 = 1.0f / den0, i1 = 1.0f / den1;
        #pragma unroll
        for (int nt = 0; nt < 8; nt++) {
            const int col = h * 64 + nt * 8 + (lane & 3) * 2;
            *reinterpret_cast<__half2*>(A16 + (size_t)row * 768 + col) =
                __floats2half2_rn(acc[nt][0] * i0, acc[nt][1] * i0);
            *reinterpret_cast<__half2*>(A16 + (size_t)(row + 8) * 768 + col) =
                __floats2half2_rn(acc[nt][2] * i1, acc[nt][3] * i1);
        }
    }
}

// ---------------------------------------------------------------------------
extern "C" void kernel_launch(void* const* d_in, const int* in_sizes, int n_in,
                              void* d_out, int out_size)
{
    const float* x    = (const float*)d_in[0];
    const float* mask = (const float*)d_in[1];
    const float* Wq   = (const float*)d_in[2];
    const float* bq   = (const float*)d_in[3];
    const float* Wk   = (const float*)d_in[4];
    const float* bk   = (const float*)d_in[5];
    const float* Wv   = (const float*)d_in[6];
    const float* bv   = (const float*)d_in[7];
    const float* Wo   = (const float*)d_in[8];
    const float* bo   = (const float*)d_in[9];
    float* out = (float*)d_out;

    float *biasc;
    __half *qkv16, *xh, *a16, *wh, *woh;
    cudaGetSymbolAddress((void**)&qkv16, g_qkv16);
    cudaGetSymbolAddress((void**)&xh,    g_xh);
    cudaGetSymbolAddress((void**)&a16,   g_a16);
    cudaGetSymbolAddress((void**)&wh,    g_wh);
    cudaGetSymbolAddress((void**)&woh,   g_woh);
    cudaGetSymbolAddress((void**)&biasc, g_biasc);

    cudaFuncSetAttribute(gemm_f16, cudaFuncAttributeMaxDynamicSharedMemorySize, F_SMEM);

    // prep
    cvt_x_kernel<<<(int)(((size_t)M * 768) / 8 / 256), 256>>>(x, xh);
    wt16_all_kernel<<<dim3(24, 24, 4), dim3(32, 8)>>>(Wq, Wk, Wv, Wo,
                                                      bq, bk, bv,
                                                      wh, woh, biasc);

    // merged QKV projection -> fp16 (single-term)
    gemm_f16<<<dim3(18, 512), 256, F_SMEM>>>(xh, wh, biasc, mask,
                                             nullptr, qkv16, 1);

    // linear-attention core (tensor cores)
    kv_tc_kernel<<<dim3(Bb * Hh, 4), 128>>>(qkv16);
    num_tc_kernel<<<dim3(Bb * Hh, Ss / 256), 128>>>(qkv16, a16);

    // output projection -> fp32 d_out (single-term)
    gemm_f16<<<dim3(6, 512), 256, F_SMEM>>>(a16, woh, bo, mask,
                                            out, nullptr, 0);
}

// round 15
// speedup vs baseline: 1.3100x; 1.0027x over previous
#include <cuda_runtime.h>
#include <cuda_fp16.h>
#include <math.h>
#include <stdint.h>

// Problem constants
#define Bb   16
#define Ss   4096
#define Hh   12
#define Dd   64
constexpr int M = Bb * Ss;   // 65536
constexpr int NQKV = 2304;   // merged Q|K|V columns

// ---------------------------------------------------------------------------
// Scratch (device globals)
// ---------------------------------------------------------------------------
__device__ __half g_qkv16[(size_t)M * NQKV];      // Q | K | V fp16
__device__ __half g_xh[(size_t)M * 768];          // x fp16
__device__ __half g_a16[(size_t)M * 768];         // attention output fp16
__device__ __half g_wh[(size_t)NQKV * 768];       // Wqkv^T fp16
__device__ __half g_woh[768 * 768];               // Wo^T fp16
__device__ float  g_biasc[NQKV];
__device__ __half g_kvp[4][Bb * Hh][64 * 72];     // kv partials (fp16)

// ---------------------------------------------------------------------------
// PTX helpers (sm_80-compatible: cp.async, ldmatrix, mma.sync)
// ---------------------------------------------------------------------------
__device__ __forceinline__ uint32_t smem_u32(const void* p) {
    uint32_t a;
    asm("{ .reg .u64 t; cvta.to.shared.u64 t, %1; cvt.u32.u64 %0, t; }"
        : "=r"(a) : "l"(p));
    return a;
}

__device__ __forceinline__ void cpa16(uint32_t dst, const void* src) {
    asm volatile("cp.async.cg.shared.global [%0], [%1], 16;" :: "r"(dst), "l"(src) : "memory");
}
#define CP_COMMIT() asm volatile("cp.async.commit_group;" ::: "memory")
#define CP_WAIT(n)  asm volatile("cp.async.wait_group %0;" :: "n"(n) : "memory")

__device__ __forceinline__ void ldsm4(uint32_t* r, uint32_t addr) {
    asm volatile("ldmatrix.sync.aligned.m8n8.x4.shared.b16 {%0,%1,%2,%3}, [%4];"
                 : "=r"(r[0]), "=r"(r[1]), "=r"(r[2]), "=r"(r[3]) : "r"(addr));
}
__device__ __forceinline__ void ldsm4t(uint32_t* r, uint32_t addr) {
    asm volatile("ldmatrix.sync.aligned.m8n8.x4.trans.shared.b16 {%0,%1,%2,%3}, [%4];"
                 : "=r"(r[0]), "=r"(r[1]), "=r"(r[2]), "=r"(r[3]) : "r"(addr));
}
__device__ __forceinline__ void ldsm2t(uint32_t* r, uint32_t addr) {
    asm volatile("ldmatrix.sync.aligned.m8n8.x2.trans.shared.b16 {%0,%1}, [%2];"
                 : "=r"(r[0]), "=r"(r[1]) : "r"(addr));
}

__device__ __forceinline__ void mma_f16(float* c, const uint32_t* a, const uint32_t* b) {
    asm volatile(
        "mma.sync.aligned.m16n8k16.row.col.f32.f16.f16.f32 "
        "{%0,%1,%2,%3}, {%4,%5,%6,%7}, {%8,%9}, {%0,%1,%2,%3};"
        : "+f"(c[0]), "+f"(c[1]), "+f"(c[2]), "+f"(c[3])
        : "r"(a[0]), "r"(a[1]), "r"(a[2]), "r"(a[3]), "r"(b[0]), "r"(b[1]));
}

__device__ __forceinline__ float epi_f(float v, float mk, int epi) {
    if (epi >= 1) v *= mk;
    if (epi == 2) { v = (v > 0.0f) ? (v + 1.0f) : __expf(v); v *= 0.125f; }
    return v;
}

// ---------------------------------------------------------------------------
// fp16 single-term GEMM:  C = A(fp16) @ B^T   (B pre-transposed [N][K])
// CTA tile 128x128x64 (two 32-wide sub-tiles/stage), 256 threads
// (8 warps, warp tile 64x32), 3-stage cp.async ring, 2 CTAs/SM.
// ---------------------------------------------------------------------------
constexpr int F_STAGE = 32768;
constexpr int F_SMEM  = 3 * F_STAGE;
constexpr int FA = 0, FB = 16384;   // each: 2 x 8KB sub-tiles

__device__ __forceinline__ void stage_load_f16(
    uint32_t sbase,
    const __half* __restrict__ A, const __half* __restrict__ B,
    int mb, int nb, int k0, int tid)
{
    #pragma unroll
    for (int sub = 0; sub < 2; sub++) {
        const int ks0 = k0 + sub * 32;
        const uint32_t sboff = (uint32_t)sub * 8192;
        #pragma unroll
        for (int t = 0; t < 2; t++) {
            const int lin = tid + t * 256;   // 512 slots: 128 rows x 4 chunks
            const int r = lin >> 2;
            const int c = lin & 3;
            const uint32_t so = (uint32_t)r * 64 + ((uint32_t)(c ^ ((r >> 1) & 3)) << 4);
            cpa16(sbase + FA + sboff + so, A + (size_t)(mb + r) * 768 + ks0 + c * 8);
            cpa16(sbase + FB + sboff + so, B + (size_t)(nb + r) * 768 + ks0 + c * 8);
        }
    }
}

__global__ void __launch_bounds__(256, 2)
gemm_f16(const __half* __restrict__ A, const __half* __restrict__ B,
         const float* __restrict__ bias, const float* __restrict__ mask,
         float* __restrict__ C32, __half* __restrict__ C16, int mode)
{
    extern __shared__ char smraw[];
    const uint32_t sm0 = smem_u32(smraw);

    const int tid  = threadIdx.x;
    const int lane = tid & 31;
    const int warp = tid >> 5;
    const int wm = warp & 1;        // 2 warps in M -> 64 rows
    const int wn = warp >> 1;       // 4 warps in N -> 32 cols
    const int nb = blockIdx.x * 128;
    const int mb = blockIdx.y * 128;
    const int epi = (mode == 0) ? 0 : ((blockIdx.x < 12) ? 2 : 1);

    uint32_t baseA[4], maskA[4];
    const int arow0 = wm * 64 + (lane & 15);
    const uint32_t acs = (uint32_t)(lane >> 4);
    #pragma unroll
    for (int mt = 0; mt < 4; mt++) {
        const int r = arow0 + mt * 16;
        baseA[mt] = (uint32_t)r * 64;
        maskA[mt] = (uint32_t)((r >> 1) & 3);
    }
    uint32_t baseB[2], maskB[2];
    const int brow0 = wn * 32 + (lane & 7) + ((lane >> 4) << 3);
    const uint32_t bcs = (uint32_t)((lane >> 3) & 1);
    #pragma unroll
    for (int bt = 0; bt < 2; bt++) {
        const int r = brow0 + bt * 16;
        baseB[bt] = (uint32_t)r * 64;
        maskB[bt] = (uint32_t)((r >> 1) & 3);
    }

    float acc[4][4][4] = {};

    stage_load_f16(sm0 + 0 * F_STAGE, A, B, mb, nb, 0, tid);
    CP_COMMIT();
    stage_load_f16(sm0 + 1 * F_STAGE, A, B, mb, nb, 64, tid);
    CP_COMMIT();

    #pragma unroll 1
    for (int s = 0; s < 12; s++) {
        if (s < 11) { CP_WAIT(1); } else { CP_WAIT(0); }
        __syncthreads();

        const uint32_t sb = sm0 + (s % 3) * F_STAGE;
        #pragma unroll
        for (int sub = 0; sub < 2; sub++) {
            const uint32_t sbA = sb + FA + sub * 8192;
            const uint32_t sbB = sb + FB + sub * 8192;
            #pragma unroll
            for (int ks = 0; ks < 2; ks++) {
                const uint32_t kc = (uint32_t)(ks * 2);

                uint32_t bf[4][2];
                #pragma unroll
                for (int bt = 0; bt < 2; bt++) {
                    const uint32_t off = baseB[bt] + (((kc + bcs) ^ maskB[bt]) << 4);
                    uint32_t tmp[4];
                    ldsm4(tmp, sbB + off);
                    bf[2 * bt][0] = tmp[0]; bf[2 * bt][1] = tmp[1];
                    bf[2 * bt + 1][0] = tmp[2]; bf[2 * bt + 1][1] = tmp[3];
                }
                uint32_t a[4][4];
                #pragma unroll
                for (int mt = 0; mt < 4; mt++)
                    ldsm4(a[mt], sbA + baseA[mt] + (((kc + acs) ^ maskA[mt]) << 4));

                #pragma unroll
                for (int mt = 0; mt < 4; mt++)
                    #pragma unroll
                    for (int nt = 0; nt < 4; nt++)
                        mma_f16(acc[mt][nt], a[mt], bf[nt]);
            }
        }

        if (s + 2 < 12) {
            stage_load_f16(sm0 + ((s + 2) % 3) * F_STAGE, A, B,
                           mb, nb, (s + 2) * 64, tid);
            CP_COMMIT();
        }
    }

    // epilogue
    const int r0 = lane >> 2;
    const int c0 = (lane & 3) * 2;
    #pragma unroll
    for (int mt = 0; mt < 4; mt++) {
        const int mrow = mb + wm * 64 + mt * 16 + r0;
        const float mk0 = (epi >= 1) ? mask[mrow] : 1.0f;
        const float mk1 = (epi >= 1) ? mask[mrow + 8] : 1.0f;
        #pragma unroll
        for (int nt = 0; nt < 4; nt++) {
            const int col = nb + wn * 32 + nt * 8 + c0;
            const float b0 = bias[col], b1 = bias[col + 1];
            const float v00 = epi_f(acc[mt][nt][0] + b0, mk0, epi);
            const float v01 = epi_f(acc[mt][nt][1] + b1, mk0, epi);
            const float v10 = epi_f(acc[mt][nt][2] + b0, mk1, epi);
            const float v11 = epi_f(acc[mt][nt][3] + b1, mk1, epi);
            if (mode == 1) {
                *reinterpret_cast<__half2*>(C16 + (size_t)mrow * NQKV + col) =
                    __floats2half2_rn(v00, v01);
                *reinterpret_cast<__half2*>(C16 + (size_t)(mrow + 8) * NQKV + col) =
                    __floats2half2_rn(v10, v11);
            } else {
                *reinterpret_cast<float2*>(C32 + (size_t)mrow * 768 + col) =
                    make_float2(v00, v01);
                *reinterpret_cast<float2*>(C32 + (size_t)(mrow + 8) * 768 + col) =
                    make_float2(v10, v11);
            }
        }
    }
}

// ---------------------------------------------------------------------------
// Prep kernels
// ---------------------------------------------------------------------------
__global__ void __launch_bounds__(256)
cvt_x_kernel(const float* __restrict__ x, __half* __restrict__ xh)
{
    const size_t i = ((size_t)blockIdx.x * 256 + threadIdx.x) * 8;
    const float4 v0 = *reinterpret_cast<const float4*>(x + i);
    const float4 v1 = *reinterpret_cast<const float4*>(x + i + 4);
    __half2 h[4];
    h[0] = __floats2half2_rn(v0.x, v0.y);
    h[1] = __floats2half2_rn(v0.z, v0.w);
    h[2] = __floats2half2_rn(v1.x, v1.y);
    h[3] = __floats2half2_rn(v1.z, v1.w);
    *reinterpret_cast<uint4*>(xh + i) = *reinterpret_cast<uint4*>(h);
}

// transpose + fp16 convert for ALL weights in one launch; z<3 row-0 blocks
// also write the concatenated bias.
__global__ void __launch_bounds__(256)
wt16_all_kernel(const float* __restrict__ Wq, const float* __restrict__ Wk,
                const float* __restrict__ Wv, const float* __restrict__ Wo,
                const float* __restrict__ bq, const float* __restrict__ bk,
                const float* __restrict__ bv,
                __half* __restrict__ wh, __half* __restrict__ woh,
                float* __restrict__ biasc)
{
    __shared__ float t[32][33];
    const int z = blockIdx.z;
    const float* W = (z == 0) ? Wq : (z == 1) ? Wk : (z == 2) ? Wv : Wo;
    __half* dst = (z == 3) ? woh : wh + (size_t)z * 768 * 768;

    const int bx = blockIdx.x * 32, by = blockIdx.y * 32;
    const int tx = threadIdx.x, ty = threadIdx.y;

    if (z < 3 && blockIdx.y == 0 && ty == 0) {
        const float* src = (z == 0) ? bq : (z == 1) ? bk : bv;
        biasc[z * 768 + bx + tx] = src[bx + tx];
    }

    #pragma unroll
    for (int i = 0; i < 32; i += 8)
        t[ty + i][tx] = W[(size_t)(by + ty + i) * 768 + bx + tx];
    __syncthreads();
    #pragma unroll
    for (int i = 0; i < 32; i += 8)
        dst[(size_t)(bx + ty + i) * 768 + by + tx] = __float2half(t[tx][ty + i]);
}

// ---------------------------------------------------------------------------
// kv = K^T V (+ ksum in col 64) via fp16 tensor cores.
// grid (192, 4): one (b,h) x 1024-seq chunk per block, 128 threads.
// Partials stored as fp16 (halves DRAM traffic here and in num_tc).
// ---------------------------------------------------------------------------
__global__ void __launch_bounds__(128)
kv_tc_kernel(const __half* __restrict__ QKV16)
{
    __shared__ __half kb[2][64][72];
    __shared__ __half vb[2][64][72];

    const int bh = blockIdx.x, ch = blockIdx.y;
    const int b = bh / Hh, h = bh % Hh;
    const int tid = threadIdx.x, lane = tid & 31, warp = tid >> 5;

    {
        const int bf = tid >> 6, r = tid & 63;
        vb[bf][r][64] = __float2half(1.0f);
        #pragma unroll
        for (int c = 65; c < 72; c++) vb[bf][r][c] = __float2half(0.0f);
    }
    __syncthreads();

    const int chunk0 = ch * 1024;
    const int d0 = warp * 16;

    #define KV_LOAD(st, s0)                                                       \
        do {                                                                      \
            _Pragma("unroll")                                                     \
            for (int t = 0; t < 4; t++) {                                         \
                const int lin = tid + t * 128;                                    \
                const int r = lin >> 3, c = lin & 7;                              \
                const size_t base =                                               \
                    ((size_t)(b * Ss + (s0) + r)) * NQKV + h * 64 + c * 8;        \
                cpa16(smem_u32(&kb[st][r][c * 8]), QKV16 + base + 768);           \
                cpa16(smem_u32(&vb[st][r][c * 8]), QKV16 + base + 1536);          \
            }                                                                     \
            CP_COMMIT();                                                          \
        } while (0)

    float acc[9][4] = {};

    KV_LOAD(0, chunk0);
    KV_LOAD(1, chunk0 + 64);

    const int g = lane >> 3, l = lane & 7;

    #pragma unroll 1
    for (int it = 0; it < 16; it++) {
        if (it < 15) { CP_WAIT(1); } else { CP_WAIT(0); }
        __syncthreads();

        const int st = it & 1;
        #pragma unroll
        for (int ks = 0; ks < 4; ks++) {
            const int srow = ks * 16 + ((g & 2) ? 8 : 0) + l;
            const int scol = d0 + ((g & 1) ? 8 : 0);
            uint32_t a[4];
            ldsm4t(a, smem_u32(&kb[st][srow][scol]));

            uint32_t bfrag[9][2];
            const int vrow = ks * 16 + ((g & 1) ? 8 : 0) + l;
            #pragma unroll
            for (int np = 0; np < 4; np++) {
                const int vcol = np * 16 + ((g & 2) ? 8 : 0);
                uint32_t t4[4];
                ldsm4t(t4, smem_u32(&vb[st][vrow][vcol]));
                bfrag[2 * np][0] = t4[0];     bfrag[2 * np][1] = t4[1];
                bfrag[2 * np + 1][0] = t4[2]; bfrag[2 * np + 1][1] = t4[3];
            }
            {
                const int vr2 = ks * 16 + ((lane >> 3) & 1) * 8 + l;
                uint32_t t2[2];
                ldsm2t(t2, smem_u32(&vb[st][vr2][64]));
                bfrag[8][0] = t2[0]; bfrag[8][1] = t2[1];
            }
            #pragma unroll
            for (int nt = 0; nt < 9; nt++) mma_f16(acc[nt], a, bfrag[nt]);
        }
        __syncthreads();
        if (it + 2 < 16) KV_LOAD(st, chunk0 + (it + 2) * 64);
    }
    #undef KV_LOAD

    __half* dst = &g_kvp[ch][bh][0];
    const int r = lane >> 2, cp = (lane & 3) * 2;
    #pragma unroll
    for (int nt = 0; nt < 9; nt++) {
        const int col = nt * 8 + cp;
        *reinterpret_cast<__half2*>(dst + (d0 + r) * 72 + col) =
            __floats2half2_rn(acc[nt][0], acc[nt][1]);
        *reinterpret_cast<__half2*>(dst + (d0 + r + 8) * 72 + col) =
            __floats2half2_rn(acc[nt][2], acc[nt][3]);
    }
}

// ---------------------------------------------------------------------------
// num|den = Q @ kv[64x72] (col 64 = den); out = num/den -> fp16 a16.
// kv partial reduction (4 fp16 partials -> fp32 -> fp16) fused into load.
// ---------------------------------------------------------------------------
__global__ void __launch_bounds__(128)
num_tc_kernel(const __half* __restrict__ QKV16, __half* __restrict__ A16)
{
    __shared__ __half kvs[64][72];

    const int bh = blockIdx.x;
    const int b = bh / Hh, h = bh % Hh;
    const int tid = threadIdx.x, lane = tid & 31, warp = tid >> 5;
    const int s0 = blockIdx.y * 256;

    {
        __half* dst = &kvs[0][0];
        for (int i = tid * 2; i < 64 * 72; i += 256) {
            const __half2 p0 = *reinterpret_cast<const __half2*>(&g_kvp[0][bh][i]);
            const __half2 p1 = *reinterpret_cast<const __half2*>(&g_kvp[1][bh][i]);
            const __half2 p2 = *reinterpret_cast<const __half2*>(&g_kvp[2][bh][i]);
            const __half2 p3 = *reinterpret_cast<const __half2*>(&g_kvp[3][bh][i]);
            const float2 f0 = __half22float2(p0);
            const float2 f1 = __half22float2(p1);
            const float2 f2 = __half22float2(p2);
            const float2 f3 = __half22float2(p3);
            *reinterpret_cast<__half2*>(dst + i) =
                __floats2half2_rn(f0.x + f1.x + f2.x + f3.x,
                                  f0.y + f1.y + f2.y + f3.y);
        }
    }
    __syncthreads();

    uint32_t bfr[4][9][2];
    const int g = lane >> 3, l = lane & 7;
    #pragma unroll
    for (int ks = 0; ks < 4; ks++) {
        const int vrow = ks * 16 + ((g & 1) ? 8 : 0) + l;
        #pragma unroll
        for (int np = 0; np < 4; np++) {
            const int vcol = np * 16 + ((g & 2) ? 8 : 0);
            uint32_t t4[4];
            ldsm4t(t4, smem_u32(&kvs[vrow][vcol]));
            bfr[ks][2 * np][0] = t4[0];     bfr[ks][2 * np][1] = t4[1];
            bfr[ks][2 * np + 1][0] = t4[2]; bfr[ks][2 * np + 1][1] = t4[3];
        }
        const int vr2 = ks * 16 + ((lane >> 3) & 1) * 8 + l;
        uint32_t t2[2];
        ldsm2t(t2, smem_u32(&kvs[vr2][64]));
        bfr[ks][8][0] = t2[0]; bfr[ks][8][1] = t2[1];
    }

    const uint32_t* Q32 = reinterpret_cast<const uint32_t*>(QKV16);
    const int rbase = b * Ss + s0 + warp * 64;

    #pragma unroll 1
    for (int mt = 0; mt < 4; mt++) {
        float acc[9][4] = {};
        const int row = rbase + mt * 16 + (lane >> 2);
        #pragma unroll
        for (int ks = 0; ks < 4; ks++) {
            const int cb = h * 64 + ks * 16 + (lane & 3) * 2;
            uint32_t a[4];
            a[0] = Q32[((size_t)row * NQKV + cb) >> 1];
            a[1] = Q32[((size_t)(row + 8) * NQKV + cb) >> 1];
            a[2] = Q32[((size_t)row * NQKV + cb + 8) >> 1];
            a[3] = Q32[((size_t)(row + 8) * NQKV + cb + 8) >> 1];
            #pragma unroll
            for (int nt = 0; nt < 9; nt++) mma_f16(acc[nt], a, bfr[ks][nt]);
        }

        const float den0 = __shfl_sync(0xFFFFFFFFu, acc[8][0], lane & 28);
        const float den1 = __shfl_sync(0xFFFFFFFFu, acc[8][2], lane & 28);
        const float i0 = 1.0f / den0, i1 = 1.0f / den1;
        #pragma unroll
        for (int nt = 0; nt < 8; nt++) {
            const int col = h * 64 + nt * 8 + (lane & 3) * 2;
            *reinterpret_cast<__half2*>(A16 + (size_t)row * 768 + col) =
                __floats2half2_rn(acc[nt][0] * i0, acc[nt][1] * i0);
            *reinterpret_cast<__half2*>(A16 + (size_t)(row + 8) * 768 + col) =
                __floats2half2_rn(acc[nt][2] * i1, acc[nt][3] * i1);
        }
    }
}

// ---------------------------------------------------------------------------
extern "C" void kernel_launch(void* const* d_in, const int* in_sizes, int n_in,
                              void* d_out, int out_size)
{
    const float* x    = (const float*)d_in[0];
    const float* mask = (const float*)d_in[1];
    const float* Wq   = (const float*)d_in[2];
    const float* bq   = (const float*)d_in[3];
    const float* Wk   = (const float*)d_in[4];
    const float* bk   = (const float*)d_in[5];
    const float* Wv   = (const float*)d_in[6];
    const float* bv   = (const float*)d_in[7];
    const float* Wo   = (const float*)d_in[8];
    const float* bo   = (const float*)d_in[9];
    float* out = (float*)d_out;

    float *biasc;
    __half *qkv16, *xh, *a16, *wh, *woh;
    cudaGetSymbolAddress((void**)&qkv16, g_qkv16);
    cudaGetSymbolAddress((void**)&xh,    g_xh);
    cudaGetSymbolAddress((void**)&a16,   g_a16);
    cudaGetSymbolAddress((void**)&wh,    g_wh);
    cudaGetSymbolAddress((void**)&woh,   g_woh);
    cudaGetSymbolAddress((void**)&biasc, g_biasc);

    cudaFuncSetAttribute(gemm_f16, cudaFuncAttributeMaxDynamicSharedMemorySize, F_SMEM);

    // prep
    cvt_x_kernel<<<(int)(((size_t)M * 768) / 8 / 256), 256>>>(x, xh);
    wt16_all_kernel<<<dim3(24, 24, 4), dim3(32, 8)>>>(Wq, Wk, Wv, Wo,
                                                      bq, bk, bv,
                                                      wh, woh, biasc);

    // merged QKV projection -> fp16 (single-term)
    gemm_f16<<<dim3(18, 512), 256, F_SMEM>>>(xh, wh, biasc, mask,
                                             nullptr, qkv16, 1);

    // linear-attention core (tensor cores)
    kv_tc_kernel<<<dim3(Bb * Hh, 4), 128>>>(qkv16);
    num_tc_kernel<<<dim3(Bb * Hh, Ss / 256), 128>>>(qkv16, a16);

    // output projection -> fp32 d_out (single-term)
    gemm_f16<<<dim3(6, 512), 256, F_SMEM>>>(a16, woh, bo, mask,
                                            out, nullptr, 0);
}